// round 2
// baseline (speedup 1.0000x reference)
#include <cuda_runtime.h>

// BinaryMaskEdgeSmoothing: fused 3x3 laplacian + sigmoid edge mask + 3x3 gauss
// blur + lerp + threshold, single pass over the (B,C,1024,1024) f32 mask.
//
// out = ( x*(1-em) + blur*em > 0.5 ) ? 1 : 0
//   edges = 9*c - sum9           (laplacian, SAME zero padding)
//   em    = sigmoid(3*|edges|)
//   blur  = (g3_top + 2*g3_mid + g3_bot) / 16,  g3 = a + 2b + c per row
//
// HBM-bound: 256MB read + 256MB write. Strategy: vertical register-rolling
// strips. Thread owns 4 columns (aligned float4), walks 32 rows; per row it
// loads ONE float4 + 2 halo scalars (L1 hits) and keeps 3 rows of
// precomputed horizontal sums (t3 = 1,1,1 ; g3 = 1,2,1) in registers.

#define IMG_W 1024
#define IMG_H 1024
#define ROWS_PER_BLOCK 32
#define THREADS (IMG_W / 4)   // 256: one block spans the full row width

struct RowSums {
    float t[4];  // 1,1,1 horizontal sum at each of the 4 columns
    float g[4];  // 1,2,1 horizontal sum
    float c[4];  // center value
};

__device__ __forceinline__ RowSums load_row(const float* __restrict__ img,
                                            int y, int x0, bool valid) {
    RowSums r;
    if (!valid) {
        #pragma unroll
        for (int j = 0; j < 4; ++j) { r.t[j] = 0.f; r.g[j] = 0.f; r.c[j] = 0.f; }
        return r;
    }
    const float* p = img + (size_t)y * IMG_W + x0;
    float4 v = *reinterpret_cast<const float4*>(p);       // 16B-aligned
    float left  = (x0 > 0)            ? p[-1] : 0.f;      // L1 hit (neighbor's line)
    float right = (x0 + 4 < IMG_W)    ? p[4]  : 0.f;
    float e0 = left, e1 = v.x, e2 = v.y, e3 = v.z, e4 = v.w, e5 = right;

    r.t[0] = e0 + e1 + e2;  r.g[0] = r.t[0] + e1;  r.c[0] = e1;
    r.t[1] = e1 + e2 + e3;  r.g[1] = r.t[1] + e2;  r.c[1] = e2;
    r.t[2] = e2 + e3 + e4;  r.g[2] = r.t[2] + e3;  r.c[2] = e3;
    r.t[3] = e3 + e4 + e5;  r.g[3] = r.t[3] + e4;  r.c[3] = e4;
    return r;
}

__global__ void __launch_bounds__(THREADS)
edge_smooth_kernel(const float* __restrict__ in, float* __restrict__ out) {
    const int img = blockIdx.y;                 // 0..B*C-1
    const int r0  = blockIdx.x * ROWS_PER_BLOCK;
    const int x0  = threadIdx.x * 4;

    const float* ibase = in  + (size_t)img * IMG_H * IMG_W;
    float*       obase = out + (size_t)img * IMG_H * IMG_W;

    RowSums A = load_row(ibase, r0 - 1, x0, r0 > 0);
    RowSums B = load_row(ibase, r0,     x0, true);

    #pragma unroll 4
    for (int y = r0; y < r0 + ROWS_PER_BLOCK; ++y) {
        RowSums C = load_row(ibase, y + 1, x0, (y + 1) < IMG_H);

        float4 o;
        float res[4];
        #pragma unroll
        for (int j = 0; j < 4; ++j) {
            float c     = B.c[j];
            float sum9  = A.t[j] + B.t[j] + C.t[j];
            float edges = fmaf(9.f, c, -sum9);                 // laplacian
            float blur  = (A.g[j] + 2.f * B.g[j] + C.g[j]) * (1.f / 16.f);
            float em    = __fdividef(1.f, 1.f + __expf(-3.f * fabsf(edges)));
            float sm    = fmaf(em, blur - c, c);               // lerp
            res[j]      = (sm > 0.5f) ? 1.f : 0.f;
        }
        o.x = res[0]; o.y = res[1]; o.z = res[2]; o.w = res[3];
        *reinterpret_cast<float4*>(obase + (size_t)y * IMG_W + x0) = o;

        A = B; B = C;
    }
}

extern "C" void kernel_launch(void* const* d_in, const int* in_sizes, int n_in,
                              void* d_out, int out_size) {
    const float* mask = (const float*)d_in[0];   // (B,C,1024,1024) f32
    float*       out  = (float*)d_out;

    int n_imgs = in_sizes[0] / (IMG_H * IMG_W);  // B*C (=64 for the listed shape)

    dim3 grid(IMG_H / ROWS_PER_BLOCK, n_imgs);
    dim3 block(THREADS);
    edge_smooth_kernel<<<grid, block>>>(mask, out);
}

// round 3
// speedup vs baseline: 1.0940x; 1.0940x over previous
#include <cuda_runtime.h>

// BinaryMaskEdgeSmoothing: fused 3x3 laplacian + sigmoid edge mask + 3x3 gauss
// blur + lerp + threshold, single pass over the (B,C,1024,1024) f32 mask.
//
// R3: 2-row-batched software pipeline. Per loop iteration a thread issues the
// loads for TWO rows (2x LDG.128 + 4 coalesced halo scalars) before touching
// any of them, then computes and stores 2 output rows. This doubles per-warp
// outstanding DRAM bytes vs R2 (which exposed full DRAM latency every row).
// Row state is 8 floats (t3, g3 horizontal sums); center = g3 - t3.

#define IMG_W 1024
#define IMG_H 1024
#define ROWS_PER_BLOCK 32
#define THREADS (IMG_W / 4)   // 256: one block spans the full row width

struct Raw { float e0, e1, e2, e3, e4, e5; };   // left halo, 4 owned, right halo

struct Sums {
    float t[4];  // 1,1,1 horizontal sum
    float g[4];  // 1,2,1 horizontal sum  (g - t = center)
};

__device__ __forceinline__ Raw load_raw(const float* __restrict__ img,
                                        int y, int x0, bool valid) {
    Raw r;
    if (!valid) { r.e0 = r.e1 = r.e2 = r.e3 = r.e4 = r.e5 = 0.f; return r; }
    const float* p = img + (size_t)y * IMG_W + x0;
    float4 v = *reinterpret_cast<const float4*>(p);       // 16B-aligned
    r.e0 = (x0 > 0)         ? p[-1] : 0.f;                // coalesced halo line
    r.e5 = (x0 + 4 < IMG_W) ? p[4]  : 0.f;
    r.e1 = v.x; r.e2 = v.y; r.e3 = v.z; r.e4 = v.w;
    return r;
}

__device__ __forceinline__ Sums make_sums(const Raw& r) {
    Sums s;
    s.t[0] = r.e0 + r.e1 + r.e2;  s.g[0] = s.t[0] + r.e1;
    s.t[1] = r.e1 + r.e2 + r.e3;  s.g[1] = s.t[1] + r.e2;
    s.t[2] = r.e2 + r.e3 + r.e4;  s.g[2] = s.t[2] + r.e3;
    s.t[3] = r.e3 + r.e4 + r.e5;  s.g[3] = s.t[3] + r.e4;
    return s;
}

// One output row from 3 row-sums (top, mid, bot). Arithmetic identical to the
// R2 kernel that passed with rel_err = 0.
__device__ __forceinline__ float4 compute_row(const Sums& A, const Sums& B,
                                              const Sums& C) {
    float res[4];
    #pragma unroll
    for (int j = 0; j < 4; ++j) {
        float c     = B.g[j] - B.t[j];                     // center
        float sum9  = A.t[j] + B.t[j] + C.t[j];
        float edges = fmaf(9.f, c, -sum9);                 // laplacian
        float blur  = (A.g[j] + 2.f * B.g[j] + C.g[j]) * (1.f / 16.f);
        float em    = __fdividef(1.f, 1.f + __expf(-3.f * fabsf(edges)));
        float sm    = fmaf(em, blur - c, c);               // lerp
        res[j]      = (sm > 0.5f) ? 1.f : 0.f;
    }
    return make_float4(res[0], res[1], res[2], res[3]);
}

__global__ void __launch_bounds__(THREADS, 4)
edge_smooth_kernel(const float* __restrict__ in, float* __restrict__ out) {
    const int img = blockIdx.y;                 // 0..B*C-1
    const int r0  = blockIdx.x * ROWS_PER_BLOCK;
    const int x0  = threadIdx.x * 4;

    const float* ibase = in  + (size_t)img * IMG_H * IMG_W;
    float*       obase = out + (size_t)img * IMG_H * IMG_W;

    Sums A = make_sums(load_raw(ibase, r0 - 1, x0, r0 > 0));
    Sums B = make_sums(load_raw(ibase, r0,     x0, true));

    for (int y = r0; y < r0 + ROWS_PER_BLOCK; y += 2) {
        // Batch both rows' loads before any consumption (2x MLP per warp).
        Raw rc = load_raw(ibase, y + 1, x0, (y + 1) < IMG_H);
        Raw rd = load_raw(ibase, y + 2, x0, (y + 2) < IMG_H);
        Sums C = make_sums(rc);
        Sums D = make_sums(rd);

        float4 o0 = compute_row(A, B, C);
        float4 o1 = compute_row(B, C, D);
        *reinterpret_cast<float4*>(obase + (size_t)y       * IMG_W + x0) = o0;
        *reinterpret_cast<float4*>(obase + (size_t)(y + 1) * IMG_W + x0) = o1;

        A = C; B = D;
    }
}

extern "C" void kernel_launch(void* const* d_in, const int* in_sizes, int n_in,
                              void* d_out, int out_size) {
    const float* mask = (const float*)d_in[0];   // (B,C,1024,1024) f32
    float*       out  = (float*)d_out;

    int n_imgs = in_sizes[0] / (IMG_H * IMG_W);  // B*C (=64 for listed shape)

    dim3 grid(IMG_H / ROWS_PER_BLOCK, n_imgs);
    dim3 block(THREADS);
    edge_smooth_kernel<<<grid, block>>>(mask, out);
}

// round 4
// speedup vs baseline: 1.1837x; 1.0820x over previous
#include <cuda_runtime.h>

// BinaryMaskEdgeSmoothing, R4: integer-threshold form + prefetch pipeline.
//
// Inputs are {0,1}, so sum9 (3x3 box sum) and gsum (16*gaussian blur) are
// exact small integers in f32. Exhaustive enumeration of all feasible
// (c, sum9, gsum) classes through the f32 arithmetic of the R2/R3 kernel
// (verified rel_err = 0.0, including the 1+expf(-3d)->1.0 rounding cases)
// collapses sigmoid+blur+lerp+threshold to:
//
//     out = (gsum >= 9) || (gsum == 8 && c == 1 && sum9 >= 4)
//
// Memory: vertical register-rolling strips, 2 output rows per iteration,
// with next iteration's 2 raw rows prefetched before computing the current
// ones (2 LDG.128 per warp continuously in flight).

#define IMG_W 1024
#define IMG_H 1024
#define ROWS_PER_BLOCK 32
#define THREADS (IMG_W / 4)   // 256: block spans full row width

struct Raw { float e0, e1, e2, e3, e4, e5; };   // left halo, 4 owned, right halo

struct Sums {
    float t[4];  // 1,1,1 horizontal sum
    float g[4];  // 1,2,1 horizontal sum   (g - t = center)
};

__device__ __forceinline__ Raw load_raw(const float* __restrict__ p,
                                        bool has_left, bool has_right,
                                        bool valid) {
    Raw r;
    if (!valid) { r.e0 = r.e1 = r.e2 = r.e3 = r.e4 = r.e5 = 0.f; return r; }
    float4 v = *reinterpret_cast<const float4*>(p);   // 16B-aligned
    r.e0 = has_left  ? p[-1] : 0.f;                   // L1-resident halo
    r.e5 = has_right ? p[4]  : 0.f;
    r.e1 = v.x; r.e2 = v.y; r.e3 = v.z; r.e4 = v.w;
    return r;
}

__device__ __forceinline__ Sums make_sums(const Raw& r) {
    Sums s;
    s.t[0] = r.e0 + r.e1 + r.e2;  s.g[0] = s.t[0] + r.e1;
    s.t[1] = r.e1 + r.e2 + r.e3;  s.g[1] = s.t[1] + r.e2;
    s.t[2] = r.e2 + r.e3 + r.e4;  s.g[2] = s.t[2] + r.e3;
    s.t[3] = r.e3 + r.e4 + r.e5;  s.g[3] = s.t[3] + r.e4;
    return s;
}

__device__ __forceinline__ float4 compute_row(const Sums& A, const Sums& B,
                                              const Sums& C) {
    float res[4];
    #pragma unroll
    for (int j = 0; j < 4; ++j) {
        float sum9 = A.t[j] + B.t[j] + C.t[j];                 // 0..9 exact
        float gsum = fmaf(2.f, B.g[j], A.g[j]) + C.g[j];       // 0..16 exact
        float cen  = B.g[j] - B.t[j];                          // 0 or 1
        bool hi = gsum > 8.5f;
        bool lo = (gsum > 7.5f) & (cen > 0.5f) & (sum9 > 3.5f);
        res[j] = (hi | lo) ? 1.f : 0.f;
    }
    return make_float4(res[0], res[1], res[2], res[3]);
}

__global__ void __launch_bounds__(THREADS, 4)
edge_smooth_kernel(const float* __restrict__ in, float* __restrict__ out) {
    const int img = blockIdx.y;                 // 0..B*C-1
    const int r0  = blockIdx.x * ROWS_PER_BLOCK;
    const int x0  = threadIdx.x * 4;

    const float* ib = in  + (size_t)img * IMG_H * IMG_W + x0;
    float*       ob = out + (size_t)img * IMG_H * IMG_W + x0;

    const bool has_l = (x0 > 0);
    const bool has_r = (x0 + 4 < IMG_W);
    // Highest row index this strip ever needs is r0 + ROWS_PER_BLOCK.
    const int  hi_row = min(r0 + ROWS_PER_BLOCK + 1, IMG_H);

    // Prime: sums for rows r0-1, r0; raw rows r0+1, r0+2 in flight.
    Sums A = make_sums(load_raw(ib + (size_t)(r0 - 1) * IMG_W, has_l, has_r, r0 > 0));
    Sums B = make_sums(load_raw(ib + (size_t)r0 * IMG_W,       has_l, has_r, true));
    Raw  rc = load_raw(ib + (size_t)(r0 + 1) * IMG_W, has_l, has_r, (r0 + 1) < hi_row);
    Raw  rd = load_raw(ib + (size_t)(r0 + 2) * IMG_W, has_l, has_r, (r0 + 2) < hi_row);

    for (int y = r0; y < r0 + ROWS_PER_BLOCK; y += 2) {
        // Prefetch next iteration's rows before touching this iteration's data.
        Raw re = load_raw(ib + (size_t)(y + 3) * IMG_W, has_l, has_r, (y + 3) < hi_row);
        Raw rf = load_raw(ib + (size_t)(y + 4) * IMG_W, has_l, has_r, (y + 4) < hi_row);

        Sums C = make_sums(rc);
        Sums D = make_sums(rd);

        float4 o0 = compute_row(A, B, C);
        float4 o1 = compute_row(B, C, D);
        *reinterpret_cast<float4*>(ob + (size_t)y       * IMG_W) = o0;
        *reinterpret_cast<float4*>(ob + (size_t)(y + 1) * IMG_W) = o1;

        A = C; B = D; rc = re; rd = rf;
    }
}

extern "C" void kernel_launch(void* const* d_in, const int* in_sizes, int n_in,
                              void* d_out, int out_size) {
    const float* mask = (const float*)d_in[0];   // (B,C,1024,1024) f32
    float*       out  = (float*)d_out;

    int n_imgs = in_sizes[0] / (IMG_H * IMG_W);  // B*C

    dim3 grid(IMG_H / ROWS_PER_BLOCK, n_imgs);
    dim3 block(THREADS);
    edge_smooth_kernel<<<grid, block>>>(mask, out);
}

// round 5
// speedup vs baseline: 1.2644x; 1.0681x over previous
#include <cuda_runtime.h>

// BinaryMaskEdgeSmoothing, R5: 8-columns-per-thread (2x float4) register-rolling
// strips + integer threshold rule + 1-iteration prefetch.
//
// Inputs are {0,1}; exhaustive case analysis through the verified f32 pipeline
// (R2/R3, rel_err = 0.0) collapses sigmoid+blur+lerp+threshold to:
//     out = (gsum >= 9) || (gsum == 8 && c == 1 && sum9 >= 4)
// where sum9 = 3x3 box sum, gsum = 16*gaussian blur (both exact ints in f32).
//
// Memory model: each thread owns cols [8t, 8t+8) of a 32-row strip, walks rows
// 2 at a time, keeps 2 rows of horizontal sums + 2 prefetched raw rows in
// registers -> 4 LDG.128 in flight per thread (2x the R4 kernel), halo scalar
// loads amortized over 8 columns.

#define IMG_W 1024
#define IMG_H 1024
#define ROWS_PER_BLOCK 32
#define THREADS (IMG_W / 8)   // 128: block spans full row width

struct Raw  { float e[10]; };          // left halo, 8 owned, right halo
struct Sums { float t[8]; float g[8]; };  // 1,1,1 and 1,2,1 horizontal sums

__device__ __forceinline__ Raw load_raw(const float* __restrict__ p,
                                        bool has_left, bool has_right,
                                        bool valid) {
    Raw r;
    if (!valid) {
        #pragma unroll
        for (int j = 0; j < 10; ++j) r.e[j] = 0.f;
        return r;
    }
    float4 v0 = *reinterpret_cast<const float4*>(p);       // 16B-aligned
    float4 v1 = *reinterpret_cast<const float4*>(p + 4);
    r.e[0] = has_left  ? p[-1] : 0.f;                      // L1-resident halo
    r.e[9] = has_right ? p[8]  : 0.f;
    r.e[1] = v0.x; r.e[2] = v0.y; r.e[3] = v0.z; r.e[4] = v0.w;
    r.e[5] = v1.x; r.e[6] = v1.y; r.e[7] = v1.z; r.e[8] = v1.w;
    return r;
}

__device__ __forceinline__ Sums make_sums(const Raw& r) {
    Sums s;
    #pragma unroll
    for (int j = 0; j < 8; ++j) {
        s.t[j] = r.e[j] + r.e[j + 1] + r.e[j + 2];
        s.g[j] = s.t[j] + r.e[j + 1];
    }
    return s;
}

__device__ __forceinline__ void compute_row(const Sums& A, const Sums& B,
                                            const Sums& C, float* __restrict__ res) {
    #pragma unroll
    for (int j = 0; j < 8; ++j) {
        float sum9 = A.t[j] + B.t[j] + C.t[j];              // 0..9 exact
        float gsum = fmaf(2.f, B.g[j], A.g[j]) + C.g[j];    // 0..16 exact
        float cen  = B.g[j] - B.t[j];                       // 0 or 1
        bool hi = gsum > 8.5f;
        bool lo = (gsum > 7.5f) & (cen > 0.5f) & (sum9 > 3.5f);
        res[j] = (hi | lo) ? 1.f : 0.f;
    }
}

__device__ __forceinline__ void store_row(float* __restrict__ p,
                                          const float* __restrict__ res) {
    *reinterpret_cast<float4*>(p)     = make_float4(res[0], res[1], res[2], res[3]);
    *reinterpret_cast<float4*>(p + 4) = make_float4(res[4], res[5], res[6], res[7]);
}

__global__ void __launch_bounds__(THREADS, 5)
edge_smooth_kernel(const float* __restrict__ in, float* __restrict__ out) {
    const int img = blockIdx.y;                 // 0..B*C-1
    const int r0  = blockIdx.x * ROWS_PER_BLOCK;
    const int x0  = threadIdx.x * 8;

    const float* ib = in  + (size_t)img * IMG_H * IMG_W + x0;
    float*       ob = out + (size_t)img * IMG_H * IMG_W + x0;

    const bool has_l = (x0 > 0);
    const bool has_r = (x0 + 8 < IMG_W);
    // Highest row index this strip ever consumes.
    const int  hi_row = min(r0 + ROWS_PER_BLOCK + 1, IMG_H);

    // Prime: sums for rows r0-1, r0; raw rows r0+1, r0+2 in flight.
    Sums A = make_sums(load_raw(ib + (size_t)(r0 - 1) * IMG_W, has_l, has_r, r0 > 0));
    Sums B = make_sums(load_raw(ib + (size_t)r0 * IMG_W,       has_l, has_r, true));
    Raw  rc = load_raw(ib + (size_t)(r0 + 1) * IMG_W, has_l, has_r, (r0 + 1) < hi_row);
    Raw  rd = load_raw(ib + (size_t)(r0 + 2) * IMG_W, has_l, has_r, (r0 + 2) < hi_row);

    for (int y = r0; y < r0 + ROWS_PER_BLOCK; y += 2) {
        // Prefetch next iteration's rows before consuming this iteration's.
        Raw re = load_raw(ib + (size_t)(y + 3) * IMG_W, has_l, has_r, (y + 3) < hi_row);
        Raw rf = load_raw(ib + (size_t)(y + 4) * IMG_W, has_l, has_r, (y + 4) < hi_row);

        Sums C = make_sums(rc);
        Sums D = make_sums(rd);

        float res0[8], res1[8];
        compute_row(A, B, C, res0);
        compute_row(B, C, D, res1);
        store_row(ob + (size_t)y       * IMG_W, res0);
        store_row(ob + (size_t)(y + 1) * IMG_W, res1);

        A = C; B = D; rc = re; rd = rf;
    }
}

extern "C" void kernel_launch(void* const* d_in, const int* in_sizes, int n_in,
                              void* d_out, int out_size) {
    const float* mask = (const float*)d_in[0];   // (B,C,1024,1024) f32
    float*       out  = (float*)d_out;

    int n_imgs = in_sizes[0] / (IMG_H * IMG_W);  // B*C

    dim3 grid(IMG_H / ROWS_PER_BLOCK, n_imgs);
    dim3 block(THREADS);
    edge_smooth_kernel<<<grid, block>>>(mask, out);
}

// round 6
// speedup vs baseline: 1.2775x; 1.0103x over previous
#include <cuda_runtime.h>

// BinaryMaskEdgeSmoothing, R6: shuffle-based halo exchange.
//
// Binary inputs => sum9 (3x3 box) and gsum (16*gauss) are exact small ints in
// f32. Verified-equivalent rule (rel_err = 0.0 since R4):
//     out = (gsum >= 9) || (gsum == 8 && cen == 1 && sum9 >= 4)
// implemented as:  qual = 6*cen + sum9;  adj = qual>9.5 ? 0.6 : 0
//                  out  = (gsum + adj) > 8.5
// (cen=0 => sum9<=8 => qual<10, so qual>=10 <=> cen=1 && sum9>=4.)
//
// Memory: 8 cols/thread register-rolling strips, 2 rows/iter, 1-iter
// prefetch. Halo columns come from __shfl of the neighbor lane's registers;
// only lanes 0/31 issue (single-line) boundary scalar loads. This removes the
// 8-wavefront-per-warp halo LDGs that were clogging the L1tex queue in R5.

#define IMG_W 1024
#define IMG_H 1024
#define RPB   32              // rows per block
#define THREADS (IMG_W / 8)   // 128: block spans full row width

struct RawV { float4 a, b; float bl, br; };   // 8 owned cols + boundary scalars
struct Sums { float t[8]; float g[8]; };      // 1,1,1 and 1,2,1 horizontal sums

__device__ __forceinline__ RawV issue_raw(const float* __restrict__ p,
                                          bool ld_l, bool ld_r, bool valid) {
    RawV r;
    if (valid) {
        r.a  = *reinterpret_cast<const float4*>(p);        // 16B-aligned
        r.b  = *reinterpret_cast<const float4*>(p + 4);
        r.bl = ld_l ? p[-1] : 0.f;   // lane 0 only: single-line load
        r.br = ld_r ? p[8]  : 0.f;   // lane 31 only
    } else {
        r.a = make_float4(0.f, 0.f, 0.f, 0.f);
        r.b = r.a; r.bl = 0.f; r.br = 0.f;
    }
    return r;
}

__device__ __forceinline__ Sums make_sums(const RawV& r, int lane) {
    // Left halo = lane-1's e[8] (= b.w); right halo = lane+1's e[1] (= a.x).
    float e0 = __shfl_up_sync(0xFFFFFFFFu, r.b.w, 1);
    float e9 = __shfl_down_sync(0xFFFFFFFFu, r.a.x, 1);
    if (lane == 0)  e0 = r.bl;
    if (lane == 31) e9 = r.br;

    float e[10] = {e0, r.a.x, r.a.y, r.a.z, r.a.w,
                   r.b.x, r.b.y, r.b.z, r.b.w, e9};
    Sums s;
    #pragma unroll
    for (int j = 0; j < 8; ++j) {
        s.t[j] = e[j] + e[j + 1] + e[j + 2];
        s.g[j] = s.t[j] + e[j + 1];
    }
    return s;
}

__device__ __forceinline__ void compute_row(const Sums& A, const Sums& B,
                                            const Sums& C, float* __restrict__ res) {
    #pragma unroll
    for (int j = 0; j < 8; ++j) {
        float sum9 = A.t[j] + B.t[j] + C.t[j];            // 0..9 exact
        float t1   = A.g[j] + C.g[j];
        float gsum = fmaf(2.f, B.g[j], t1);               // 0..16 exact
        float cen  = B.g[j] - B.t[j];                     // 0 or 1
        float qual = fmaf(6.f, cen, sum9);                // >=10 <=> lo-qualify
        float adj  = (qual > 9.5f) ? 0.6f : 0.f;
        res[j] = (gsum + adj > 8.5f) ? 1.f : 0.f;
    }
}

__device__ __forceinline__ void store_row(float* __restrict__ p,
                                          const float* __restrict__ res) {
    *reinterpret_cast<float4*>(p)     = make_float4(res[0], res[1], res[2], res[3]);
    *reinterpret_cast<float4*>(p + 4) = make_float4(res[4], res[5], res[6], res[7]);
}

__global__ void __launch_bounds__(THREADS, 5)
edge_smooth_kernel(const float* __restrict__ in, float* __restrict__ out) {
    const int img  = blockIdx.y;                 // 0..B*C-1
    const int r0   = blockIdx.x * RPB;
    const int x0   = threadIdx.x * 8;
    const int lane = threadIdx.x & 31;

    const float* ib = in  + (size_t)img * IMG_H * IMG_W + x0;
    float*       ob = out + (size_t)img * IMG_H * IMG_W + x0;

    const bool ld_l = (lane == 0)  && (x0 > 0);
    const bool ld_r = (lane == 31) && (x0 + 8 < IMG_W);
    const int  hi_row = min(r0 + RPB + 1, IMG_H);   // last row this strip reads

    // Prime: sums for rows r0-1, r0; raw rows r0+1, r0+2 in flight.
    Sums A = make_sums(issue_raw(ib + (size_t)(r0 - 1) * IMG_W, ld_l, ld_r, r0 > 0), lane);
    Sums B = make_sums(issue_raw(ib + (size_t)r0 * IMG_W,       ld_l, ld_r, true),  lane);
    RawV rc = issue_raw(ib + (size_t)(r0 + 1) * IMG_W, ld_l, ld_r, (r0 + 1) < hi_row);
    RawV rd = issue_raw(ib + (size_t)(r0 + 2) * IMG_W, ld_l, ld_r, (r0 + 2) < hi_row);

    const float* pin = ib + (size_t)(r0 + 3) * IMG_W;   // next prefetch row
    float*       po  = ob + (size_t)r0 * IMG_W;         // next store row

    for (int y = r0; y < r0 + RPB; y += 2) {
        // Prefetch next iteration's rows before consuming this iteration's.
        RawV re = issue_raw(pin,         ld_l, ld_r, (y + 3) < hi_row);
        RawV rf = issue_raw(pin + IMG_W, ld_l, ld_r, (y + 4) < hi_row);
        pin += 2 * IMG_W;

        Sums C = make_sums(rc, lane);
        Sums D = make_sums(rd, lane);

        float res0[8], res1[8];
        compute_row(A, B, C, res0);
        compute_row(B, C, D, res1);
        store_row(po,         res0);
        store_row(po + IMG_W, res1);
        po += 2 * IMG_W;

        A = C; B = D; rc = re; rd = rf;
    }
}

extern "C" void kernel_launch(void* const* d_in, const int* in_sizes, int n_in,
                              void* d_out, int out_size) {
    const float* mask = (const float*)d_in[0];   // (B,C,1024,1024) f32
    float*       out  = (float*)d_out;

    int n_imgs = in_sizes[0] / (IMG_H * IMG_W);  // B*C

    dim3 grid(IMG_H / RPB, n_imgs);
    dim3 block(THREADS);
    edge_smooth_kernel<<<grid, block>>>(mask, out);
}